// round 12
// baseline (speedup 1.0000x reference)
#include <cuda_runtime.h>
#include <cuda_bf16.h>
#include <cstdint>

#define NTOK 4096
#define L2E  1.4426950408889634f
#define PIT  72          // smem pitch in bf16 elements
#define PITB 144         // smem pitch in bytes
#define REG  36864       // region size: 128 rows * 144B * 2 (hi+lo)

// ---------------- scratch ----------------
__device__ __nv_bfloat16 g_qth[2][4][NTOK][64];
__device__ __nv_bfloat16 g_qtl[2][4][NTOK][64];
__device__ __nv_bfloat16 g_kth[2][4][NTOK][64];
__device__ __nv_bfloat16 g_ktl[2][4][NTOK][64];
__device__ __nv_bfloat16 g_vh [2][4][64][NTOK];
__device__ __nv_bfloat16 g_vl [2][4][64][NTOK];
__device__ float g_c[2][4][NTOK];
__device__ float g_ot[2][4][NTOK][64];   // O transposed: [token j][chan c]
__device__ int   g_cnt[2][4];            // stats-tiles-done counter per (br,b)

// ---------------- helpers ----------------
__device__ __forceinline__ uint32_t smem_u32(const void* p) {
    uint32_t a;
    asm("{ .reg .u64 t; cvta.to.shared.u64 t, %1; cvt.u32.u64 %0, t; }" : "=r"(a) : "l"(p));
    return a;
}
__device__ __forceinline__ float ex2f(float x) {
    float r; asm("ex2.approx.ftz.f32 %0, %1;" : "=f"(r) : "f"(x)); return r;
}
__device__ __forceinline__ void ldsm4(uint32_t* r, uint32_t a) {
    asm volatile("ldmatrix.sync.aligned.m8n8.x4.shared.b16 {%0,%1,%2,%3}, [%4];"
                 : "=r"(r[0]), "=r"(r[1]), "=r"(r[2]), "=r"(r[3]) : "r"(a));
}
__device__ __forceinline__ void mma_bf16(float* c, const uint32_t* a, const uint32_t* b) {
    asm volatile("mma.sync.aligned.m16n8k16.row.col.f32.bf16.bf16.f32 "
                 "{%0,%1,%2,%3}, {%4,%5,%6,%7}, {%8,%9}, {%0,%1,%2,%3};"
                 : "+f"(c[0]), "+f"(c[1]), "+f"(c[2]), "+f"(c[3])
                 : "r"(a[0]), "r"(a[1]), "r"(a[2]), "r"(a[3]), "r"(b[0]), "r"(b[1]));
}
__device__ __forceinline__ uint32_t cvtb2(float a, float b) {
    uint32_t r;
    asm("cvt.rn.bf16x2.f32 %0, %1, %2;" : "=r"(r) : "f"(b), "f"(a));
    return r;
}
__device__ __forceinline__ void cp16(uint32_t d, const void* s) {
    asm volatile("cp.async.cg.shared.global [%0], [%1], 16;" :: "r"(d), "l"(s));
}
#define CP_COMMIT() asm volatile("cp.async.commit_group;" ::: "memory")
#define CP_WAIT0()  asm volatile("cp.async.wait_group 0;" ::: "memory")

// ---------------------------------------------------------------------------
// Kernel 1: fused projections -> bf16 hi/lo; also resets g_cnt for this launch
// ---------------------------------------------------------------------------
struct ProjArgs { const float* W[6]; const float* B[6]; };

__global__ void __launch_bounds__(256, 2) proj_kernel(const float* __restrict__ x, ProjArgs pa) {
    extern __shared__ char dsm[];
    float* Wt = (float*)dsm;
    float* xs = Wt + 4096;
    float* bs = xs + 4096;
    __nv_bfloat16* tsh = (__nv_bfloat16*)(bs + 64);
    __nv_bfloat16* tsl = tsh + 64 * PIT;

    int t = threadIdx.x;
    int b = blockIdx.y;
    int n0 = blockIdx.x * 256;
    int z = blockIdx.z, br = z / 3, which = z % 3;

    if (blockIdx.x == 0 && blockIdx.y == 0 && blockIdx.z == 0 && t < 8)
        ((int*)g_cnt)[t] = 0;

    const float* W = pa.W[z];
    const float* bias = pa.B[z];

    for (int idx = t; idx < 64 * 64; idx += 256) {
        int o = idx >> 6, c = idx & 63;
        Wt[c * 64 + o] = W[idx];
    }
    if (t < 64) bs[t] = bias[t];
    __syncthreads();

    const float* xb = x + (size_t)b * 64 * NTOK;
    int tx = t & 15, ty = t >> 4;

    __nv_bfloat16 (*th)[64] = (which == 0) ? g_qth[br][b] : g_kth[br][b];
    __nv_bfloat16 (*tl)[64] = (which == 0) ? g_qtl[br][b] : g_ktl[br][b];

    for (int nc = 0; nc < 256; nc += 64) {
        __syncthreads();
        for (int idx = t; idx < 64 * 16; idx += 256) {
            int c = idx >> 4, n4 = idx & 15;
            *(float4*)&xs[c * 64 + n4 * 4] = *(const float4*)&xb[c * NTOK + n0 + nc + n4 * 4];
        }
        __syncthreads();

        float acc[4][4] = {};
        #pragma unroll 8
        for (int c = 0; c < 64; c++) {
            float wv[4], xv[4];
            *(float4*)wv = *(float4*)&Wt[c * 64 + ty * 4];
            *(float4*)xv = *(float4*)&xs[c * 64 + tx * 4];
            #pragma unroll
            for (int i = 0; i < 4; i++)
                #pragma unroll
                for (int j = 0; j < 4; j++)
                    acc[i][j] += wv[i] * xv[j];
        }

        if (which < 2) {
            #pragma unroll
            for (int j = 0; j < 4; j++) {
                int nl = tx * 4 + j;
                #pragma unroll
                for (int i = 0; i < 4; i++) {
                    int o = ty * 4 + i;
                    float v = acc[i][j] + bs[o];
                    __nv_bfloat16 h = __float2bfloat16(v);
                    tsh[nl * PIT + o] = h;
                    tsl[nl * PIT + o] = __float2bfloat16(v - __bfloat162float(h));
                }
            }
            __syncthreads();
            for (int idx = t; idx < 64 * 8; idx += 256) {
                int row = idx >> 3, c8 = idx & 7;
                *(uint4*)&th[n0 + nc + row][c8 * 8] = *(uint4*)&tsh[row * PIT + c8 * 8];
                *(uint4*)&tl[n0 + nc + row][c8 * 8] = *(uint4*)&tsl[row * PIT + c8 * 8];
            }
        } else {
            #pragma unroll
            for (int i = 0; i < 4; i++) {
                int o = ty * 4 + i;
                float bb = bs[o];
                float v0 = acc[i][0] + bb, v1 = acc[i][1] + bb;
                float v2 = acc[i][2] + bb, v3 = acc[i][3] + bb;
                uint2 hp, lp;
                hp.x = cvtb2(v0, v1);
                hp.y = cvtb2(v2, v3);
                float h0 = __uint_as_float(hp.x << 16);
                float h1 = __uint_as_float(hp.x & 0xFFFF0000u);
                float h2 = __uint_as_float(hp.y << 16);
                float h3 = __uint_as_float(hp.y & 0xFFFF0000u);
                lp.x = cvtb2(v0 - h0, v1 - h1);
                lp.y = cvtb2(v2 - h2, v3 - h3);
                *(uint2*)&g_vh[br][b][o][n0 + nc + tx * 4] = hp;
                *(uint2*)&g_vl[br][b][o][n0 + nc + tx * 4] = lp;
            }
        }
    }
}

// ---------------------------------------------------------------------------
// Kernel 2: FUSED attention. CTA = (jt, br, b), grid 256, all co-resident.
// Phase A: stats for i-tile jt -> g_c, count up.
// Phase B: wait count==32 for (br,b), then pv for j-tile jt.
// ---------------------------------------------------------------------------
__global__ void __launch_bounds__(256, 2) attn_kernel() {
    extern __shared__ char dyn[];
    __shared__ float zbuf[128];
    __shared__ float cs[2][64];

    int t = threadIdx.x, w = t >> 5, lane = t & 31;
    int jt = blockIdx.x, br = blockIdx.y, b = blockIdx.z;
    int i0 = jt * 128;           // phase A tile
    int j0 = jt * 128;           // phase B tile

    uint32_t base = smem_u32(dyn);
    uint32_t boff4 = (lane & 7) * PITB + ((lane >> 3) & 1) * 16 + (lane >> 4) * (8 * PITB);

    // ===================== PHASE A: stats =====================
    {
        int rg = w >> 1, cg = w & 1;
        if (t < 128) zbuf[t] = 0.f;

        for (int idx = t; idx < 128 * 8; idx += 256) {
            int row = idx >> 3, c8 = idx & 7;
            uint32_t off = row * PITB + c8 * 16;
            cp16(base + REG + off,        &g_qth[br][b][i0 + row][c8 * 8]);
            cp16(base + REG + 18432 + off,&g_qtl[br][b][i0 + row][c8 * 8]);
            cp16(base + off,              &g_kth[br][b][row][c8 * 8]);
            cp16(base + 18432 + off,      &g_ktl[br][b][row][c8 * 8]);
        }
        CP_COMMIT();
        CP_WAIT0();
        __syncthreads();

        uint32_t aQh[2][4][4], aQl[2][4][4];
        #pragma unroll
        for (int m = 0; m < 2; m++) {
            uint32_t ah = base + REG +         (32 * rg + 16 * m + (lane & 15)) * PITB + (lane >> 4) * 16;
            uint32_t al = base + REG + 18432 + (32 * rg + 16 * m + (lane & 15)) * PITB + (lane >> 4) * 16;
            #pragma unroll
            for (int k = 0; k < 4; k++) { ldsm4(aQh[m][k], ah + k * 32); ldsm4(aQl[m][k], al + k * 32); }
        }

        float zr[4] = {0.f, 0.f, 0.f, 0.f};

        for (int kt = 0; kt < 32; kt++) {
            uint32_t cur = base + (kt & 1) * REG;
            uint32_t nxt = base + ((kt + 1) & 1) * REG;

            CP_WAIT0();
            __syncthreads();

            if (kt + 1 < 32) {
                for (int idx = t; idx < 128 * 8; idx += 256) {
                    int row = idx >> 3, c8 = idx & 7;
                    uint32_t off = row * PITB + c8 * 16;
                    cp16(nxt + off,         &g_kth[br][b][(kt + 1) * 128 + row][c8 * 8]);
                    cp16(nxt + 18432 + off, &g_ktl[br][b][(kt + 1) * 128 + row][c8 * 8]);
                }
                CP_COMMIT();
            }

            uint32_t kh0 = cur, kl0 = cur + 18432;

            #pragma unroll
            for (int np = 0; np < 4; np++) {
                float s4[2][2][4] = {};
                #pragma unroll
                for (int k = 0; k < 4; k++) {
                    uint32_t bh[4], bl[4];
                    uint32_t cb = (64 * cg + 16 * np) * PITB + boff4 + k * 32;
                    ldsm4(bh, kh0 + cb);
                    ldsm4(bl, kl0 + cb);
                    #pragma unroll
                    for (int p = 0; p < 2; p++)
                        #pragma unroll
                        for (int m = 0; m < 2; m++) mma_bf16(s4[p][m], aQh[m][k], &bh[2 * p]);
                    #pragma unroll
                    for (int p = 0; p < 2; p++)
                        #pragma unroll
                        for (int m = 0; m < 2; m++) mma_bf16(s4[p][m], aQh[m][k], &bl[2 * p]);
                    #pragma unroll
                    for (int p = 0; p < 2; p++)
                        #pragma unroll
                        for (int m = 0; m < 2; m++) mma_bf16(s4[p][m], aQl[m][k], &bh[2 * p]);
                }
                #pragma unroll
                for (int p = 0; p < 2; p++)
                    #pragma unroll
                    for (int m = 0; m < 2; m++) {
                        zr[m * 2 + 0] += ex2f(s4[p][m][0] * L2E) + ex2f(s4[p][m][1] * L2E);
                        zr[m * 2 + 1] += ex2f(s4[p][m][2] * L2E) + ex2f(s4[p][m][3] * L2E);
                    }
            }
        }

        #pragma unroll
        for (int q = 0; q < 4; q++) {
            zr[q] += __shfl_xor_sync(0xffffffffu, zr[q], 1);
            zr[q] += __shfl_xor_sync(0xffffffffu, zr[q], 2);
        }
        if ((lane & 3) == 0) {
            int rbase = 32 * rg + (lane >> 2);
            atomicAdd(&zbuf[rbase],      zr[0]);
            atomicAdd(&zbuf[rbase + 8],  zr[1]);
            atomicAdd(&zbuf[rbase + 16], zr[2]);
            atomicAdd(&zbuf[rbase + 24], zr[3]);
        }
        __syncthreads();
        if (t < 128) g_c[br][b][i0 + t] = __log2f(zbuf[t]);
    }

    // publish + wait
    __threadfence();
    __syncthreads();
    if (t == 0) {
        atomicAdd(&g_cnt[br][b], 1);
        int v;
        do {
            asm volatile("ld.global.acquire.gpu.b32 %0, [%1];"
                         : "=r"(v) : "l"(&g_cnt[br][b]) : "memory");
            if (v < 32) __nanosleep(256);
        } while (v < 32);
    }
    __syncthreads();

    // ===================== PHASE B: pv =====================
    {
        for (int idx = t; idx < 128 * 8; idx += 256) {
            int row = idx >> 3, c8 = idx & 7;
            uint32_t off = row * PITB + c8 * 16;
            cp16(base + off,         &g_kth[br][b][j0 + row][c8 * 8]);
            cp16(base + 18432 + off, &g_ktl[br][b][j0 + row][c8 * 8]);
        }
        for (int idx = t; idx < 64 * 8; idx += 256) {
            int row = idx >> 3, c8 = idx & 7;
            uint32_t off = row * PITB + c8 * 16;
            cp16(base + REG + off,         &g_qth[br][b][row][c8 * 8]);
            cp16(base + REG + 9216 + off,  &g_qtl[br][b][row][c8 * 8]);
            cp16(base + REG + 18432 + off, &g_vh[br][b][row][c8 * 8]);
            cp16(base + REG + 27648 + off, &g_vl[br][b][row][c8 * 8]);
        }
        CP_COMMIT();
        if (t < 64) cs[0][t] = __ldcg(&g_c[br][b][t]);
        CP_WAIT0();
        __syncthreads();

        uint32_t aKh[4][4], aKl[4][4];
        {
            uint32_t ah = base +         (16 * w + (lane & 15)) * PITB + (lane >> 4) * 16;
            uint32_t al = base + 18432 + (16 * w + (lane & 15)) * PITB + (lane >> 4) * 16;
            #pragma unroll
            for (int k = 0; k < 4; k++) { ldsm4(aKh[k], ah + k * 32); ldsm4(aKl[k], al + k * 32); }
        }

        float oacc[8][4] = {};

        for (int it = 0; it < 64; it++) {
            uint32_t cur = base + ((it & 1) ? 0 : REG);
            uint32_t nxt = base + ((it & 1) ? REG : 0);

            CP_WAIT0();
            __syncthreads();

            if (it + 1 < 64) {
                int i1 = (it + 1) * 64;
                for (int idx = t; idx < 64 * 8; idx += 256) {
                    int row = idx >> 3, c8 = idx & 7;
                    uint32_t off = row * PITB + c8 * 16;
                    cp16(nxt + off,         &g_qth[br][b][i1 + row][c8 * 8]);
                    cp16(nxt + 9216 + off,  &g_qtl[br][b][i1 + row][c8 * 8]);
                    cp16(nxt + 18432 + off, &g_vh[br][b][row][i1 + c8 * 8]);
                    cp16(nxt + 27648 + off, &g_vl[br][b][row][i1 + c8 * 8]);
                }
                CP_COMMIT();
                if (t < 64) cs[(it + 1) & 1][t] = __ldcg(&g_c[br][b][i1 + t]);
            }

            uint32_t qh0 = cur, ql0 = cur + 9216;
            uint32_t vh0 = cur + 18432, vl0 = cur + 27648;
            const float* csc = cs[it & 1];

            #pragma unroll
            for (int h = 0; h < 2; h++) {
                float s4[4][4] = {};
                #pragma unroll
                for (int k = 0; k < 4; k++) {
                    uint32_t bh[2][4], bl[2][4];
                    #pragma unroll
                    for (int qp = 0; qp < 2; qp++) {
                        uint32_t cb = (8 * (4 * h + 2 * qp)) * PITB + boff4 + k * 32;
                        ldsm4(bh[qp], qh0 + cb);
                        ldsm4(bl[qp], ql0 + cb);
                    }
                    #pragma unroll
                    for (int q = 0; q < 4; q++) mma_bf16(s4[q], aKh[k], &bh[q >> 1][2 * (q & 1)]);
                    #pragma unroll
                    for (int q = 0; q < 4; q++) mma_bf16(s4[q], aKh[k], &bl[q >> 1][2 * (q & 1)]);
                    #pragma unroll
                    for (int q = 0; q < 4; q++) mma_bf16(s4[q], aKl[k], &bh[q >> 1][2 * (q & 1)]);
                }

                #pragma unroll
                for (int kc = 0; kc < 2; kc++) {
                    uint32_t aP[4], aPl[4];
                    #pragma unroll
                    for (int qq = 0; qq < 2; qq++) {
                        int q = 2 * kc + qq;
                        int col = 8 * (4 * h + q) + 2 * (lane & 3);
                        float2 cc = *(float2*)&csc[col];
                        float p0 = ex2f(fmaf(s4[q][0], L2E, -cc.x));
                        float p1 = ex2f(fmaf(s4[q][1], L2E, -cc.y));
                        float p2 = ex2f(fmaf(s4[q][2], L2E, -cc.x));
                        float p3 = ex2f(fmaf(s4[q][3], L2E, -cc.y));
                        uint32_t u01 = cvtb2(p0, p1);
                        uint32_t u23 = cvtb2(p2, p3);
                        aP[qq * 2 + 0] = u01;
                        aP[qq * 2 + 1] = u23;
                        float h0 = __uint_as_float(u01 << 16);
                        float h1 = __uint_as_float(u01 & 0xFFFF0000u);
                        float h2 = __uint_as_float(u23 << 16);
                        float h3 = __uint_as_float(u23 & 0xFFFF0000u);
                        aPl[qq * 2 + 0] = cvtb2(p0 - h0, p1 - h1);
                        aPl[qq * 2 + 1] = cvtb2(p2 - h2, p3 - h3);
                    }

                    uint32_t kb = (uint32_t)(64 * h + 32 * kc);
                    #pragma unroll
                    for (int cg2 = 0; cg2 < 2; cg2++) {
                        uint32_t bVh[2][4], bVl[2][4];
                        #pragma unroll
                        for (int cp = 0; cp < 2; cp++) {
                            uint32_t cb = (8 * (4 * cg2 + 2 * cp)) * PITB + boff4 + kb;
                            ldsm4(bVh[cp], vh0 + cb);
                            ldsm4(bVl[cp], vl0 + cb);
                        }
                        #pragma unroll
                        for (int c4 = 0; c4 < 4; c4++)
                            mma_bf16(oacc[4 * cg2 + c4], aP, &bVh[c4 >> 1][2 * (c4 & 1)]);
                        #pragma unroll
                        for (int c4 = 0; c4 < 4; c4++)
                            mma_bf16(oacc[4 * cg2 + c4], aP, &bVl[c4 >> 1][2 * (c4 & 1)]);
                        #pragma unroll
                        for (int c4 = 0; c4 < 4; c4++)
                            mma_bf16(oacc[4 * cg2 + c4], aPl, &bVh[c4 >> 1][2 * (c4 & 1)]);
                    }
                }
            }
        }

        int jr = j0 + 16 * w + (lane >> 2);
        #pragma unroll
        for (int ct = 0; ct < 8; ct++) {
            int c0 = 8 * ct + 2 * (lane & 3);
            *(float2*)&g_ot[br][b][jr][c0]     = make_float2(oacc[ct][0], oacc[ct][1]);
            *(float2*)&g_ot[br][b][jr + 8][c0] = make_float2(oacc[ct][2], oacc[ct][3]);
        }
    }
}

// ---------------------------------------------------------------------------
// Kernel 3: final fuse conv, reads g_ot with smem transpose staging
// ---------------------------------------------------------------------------
__global__ void __launch_bounds__(256, 2) final_kernel(const float* __restrict__ Wf,
                             const float* __restrict__ bf,
                             const float* __restrict__ g1p,
                             const float* __restrict__ g2p,
                             float* __restrict__ y) {
    extern __shared__ float smf[];
    float (*Wt)[64] = (float(*)[64])smf;
    float (*csm)[68] = (float(*)[68])(smf + 128 * 64);
    float* bs = smf + 128 * 64 + 128 * 68;

    int t = threadIdx.x;
    int b = blockIdx.y;
    int n0 = blockIdx.x * 128;
    float gg1 = *g1p, gg2 = *g2p;

    for (int idx = t; idx < 64 * 128; idx += 256) {
        int o = idx >> 7, c = idx & 127;
        Wt[c][o] = Wf[idx];
    }
    if (t < 64) bs[t] = bf[t];
    __syncthreads();

    int tx = t & 15, ty = t >> 4;
    for (int nc = 0; nc < 128; nc += 64) {
        __syncthreads();
        for (int idx = t; idx < 2048; idx += 256) {
            int br2 = idx >> 10, rem = idx & 1023, n = rem >> 4, c4 = rem & 15;
            float4 v4 = *(const float4*)&g_ot[br2][b][n0 + nc + n][c4 * 4];
            float g = br2 ? gg2 : gg1;
            csm[br2 * 64 + c4 * 4 + 0][n] = v4.x * g;
            csm[br2 * 64 + c4 * 4 + 1][n] = v4.y * g;
            csm[br2 * 64 + c4 * 4 + 2][n] = v4.z * g;
            csm[br2 * 64 + c4 * 4 + 3][n] = v4.w * g;
        }
        __syncthreads();

        float acc[4][4] = {};
        #pragma unroll 8
        for (int c = 0; c < 128; c++) {
            float wv[4], xv[4];
            *(float4*)wv = *(float4*)&Wt[c][ty * 4];
            *(float4*)xv = *(float4*)&csm[c][tx * 4];
            #pragma unroll
            for (int i = 0; i < 4; i++)
                #pragma unroll
                for (int j = 0; j < 4; j++)
                    acc[i][j] += wv[i] * xv[j];
        }
        #pragma unroll
        for (int i = 0; i < 4; i++) {
            int o = ty * 4 + i;
            float bb = bs[o];
            float4 r = make_float4(acc[i][0] + bb, acc[i][1] + bb,
                                   acc[i][2] + bb, acc[i][3] + bb);
            *(float4*)&y[(size_t)b * 64 * NTOK + o * NTOK + n0 + nc + tx * 4] = r;
        }
    }
}

// ---------------------------------------------------------------------------
extern "C" void kernel_launch(void* const* d_in, const int* in_sizes, int n_in,
                              void* d_out, int out_size) {
    const float* x  = (const float*)d_in[0];
    const float* g1 = (const float*)d_in[13];
    const float* g2 = (const float*)d_in[14];
    const float* Wf = (const float*)d_in[15];
    const float* bf = (const float*)d_in[16];
    float* y = (float*)d_out;

    ProjArgs pa;
    for (int mi = 0; mi < 6; mi++) {
        pa.W[mi] = (const float*)d_in[1 + 2 * mi];
        pa.B[mi] = (const float*)d_in[2 + 2 * mi];
    }

    const int smP = (4096 + 4096 + 64) * 4 + 2 * 64 * PIT * 2;   // 51456
    const int smA = 2 * REG;                                     // 73728
    const int smF = (128 * 64 + 128 * 68 + 64) * 4;              // 67840

    cudaFuncSetAttribute(proj_kernel,  cudaFuncAttributeMaxDynamicSharedMemorySize, smP);
    cudaFuncSetAttribute(attn_kernel,  cudaFuncAttributeMaxDynamicSharedMemorySize, smA);
    cudaFuncSetAttribute(final_kernel, cudaFuncAttributeMaxDynamicSharedMemorySize, smF);

    proj_kernel <<<dim3(16, 4, 6), 256, smP>>>(x, pa);
    attn_kernel <<<dim3(32, 2, 4), 256, smA>>>();
    final_kernel<<<dim3(32, 4), 256, smF>>>(Wf, bf, g1, g2, y);
}

// round 13
// speedup vs baseline: 1.1715x; 1.1715x over previous
#include <cuda_runtime.h>
#include <cuda_bf16.h>
#include <cstdint>

#define NTOK 4096
#define L2E  1.4426950408889634f
#define PIT  72          // smem pitch in bf16 elements
#define PITB 144         // smem pitch in bytes
#define REG  36864       // region size: 128 rows * 144B * 2 (hi+lo)

// ---------------- scratch ----------------
__device__ __nv_bfloat16 g_qth[2][4][NTOK][64];
__device__ __nv_bfloat16 g_qtl[2][4][NTOK][64];
__device__ __nv_bfloat16 g_kth[2][4][NTOK][64];
__device__ __nv_bfloat16 g_ktl[2][4][NTOK][64];
__device__ __nv_bfloat16 g_vh [2][4][64][NTOK];
__device__ __nv_bfloat16 g_vl [2][4][64][NTOK];
__device__ float g_c[2][4][NTOK];
__device__ float g_ot[2][4][NTOK][64];   // O transposed: [token j][chan c]

// ---------------- helpers ----------------
__device__ __forceinline__ uint32_t smem_u32(const void* p) {
    uint32_t a;
    asm("{ .reg .u64 t; cvta.to.shared.u64 t, %1; cvt.u32.u64 %0, t; }" : "=r"(a) : "l"(p));
    return a;
}
__device__ __forceinline__ float ex2f(float x) {
    float r; asm("ex2.approx.ftz.f32 %0, %1;" : "=f"(r) : "f"(x)); return r;
}
__device__ __forceinline__ void ldsm4(uint32_t* r, uint32_t a) {
    asm volatile("ldmatrix.sync.aligned.m8n8.x4.shared.b16 {%0,%1,%2,%3}, [%4];"
                 : "=r"(r[0]), "=r"(r[1]), "=r"(r[2]), "=r"(r[3]) : "r"(a));
}
__device__ __forceinline__ void mma_bf16(float* c, const uint32_t* a, const uint32_t* b) {
    asm volatile("mma.sync.aligned.m16n8k16.row.col.f32.bf16.bf16.f32 "
                 "{%0,%1,%2,%3}, {%4,%5,%6,%7}, {%8,%9}, {%0,%1,%2,%3};"
                 : "+f"(c[0]), "+f"(c[1]), "+f"(c[2]), "+f"(c[3])
                 : "r"(a[0]), "r"(a[1]), "r"(a[2]), "r"(a[3]), "r"(b[0]), "r"(b[1]));
}
// packed bf16x2 convert: lo = a, hi = b (rn rounding)
__device__ __forceinline__ uint32_t cvtb2(float a, float b) {
    uint32_t r;
    asm("cvt.rn.bf16x2.f32 %0, %1, %2;" : "=r"(r) : "f"(b), "f"(a));
    return r;
}
__device__ __forceinline__ void cp16(uint32_t d, const void* s) {
    asm volatile("cp.async.cg.shared.global [%0], [%1], 16;" :: "r"(d), "l"(s));
}
#define CP_COMMIT() asm volatile("cp.async.commit_group;" ::: "memory")
#define CP_WAIT0()  asm volatile("cp.async.wait_group 0;" ::: "memory")

// ---------------------------------------------------------------------------
// Kernel 1: fused projections -> bf16 hi/lo in MMA-ready (k-contiguous) layouts
// 3 CTAs/SM for latency hiding; grid 384 = single wave.
// ---------------------------------------------------------------------------
struct ProjArgs { const float* W[6]; const float* B[6]; };

__global__ void __launch_bounds__(256, 3) proj_kernel(const float* __restrict__ x, ProjArgs pa) {
    extern __shared__ char dsm[];
    float* Wt = (float*)dsm;
    float* xs = Wt + 4096;
    float* bs = xs + 4096;
    __nv_bfloat16* tsh = (__nv_bfloat16*)(bs + 64);
    __nv_bfloat16* tsl = tsh + 64 * PIT;

    int t = threadIdx.x;
    int b = blockIdx.y;
    int n0 = blockIdx.x * 256;
    int z = blockIdx.z, br = z / 3, which = z % 3;
    const float* W = pa.W[z];
    const float* bias = pa.B[z];

    for (int idx = t; idx < 64 * 64; idx += 256) {
        int o = idx >> 6, c = idx & 63;
        Wt[c * 64 + o] = W[idx];
    }
    if (t < 64) bs[t] = bias[t];
    __syncthreads();

    const float* xb = x + (size_t)b * 64 * NTOK;
    int tx = t & 15, ty = t >> 4;

    __nv_bfloat16 (*th)[64] = (which == 0) ? g_qth[br][b] : g_kth[br][b];
    __nv_bfloat16 (*tl)[64] = (which == 0) ? g_qtl[br][b] : g_ktl[br][b];

    for (int nc = 0; nc < 256; nc += 64) {
        __syncthreads();
        for (int idx = t; idx < 64 * 16; idx += 256) {
            int c = idx >> 4, n4 = idx & 15;
            *(float4*)&xs[c * 64 + n4 * 4] = *(const float4*)&xb[c * NTOK + n0 + nc + n4 * 4];
        }
        __syncthreads();

        float acc[4][4] = {};
        #pragma unroll 8
        for (int c = 0; c < 64; c++) {
            float wv[4], xv[4];
            *(float4*)wv = *(float4*)&Wt[c * 64 + ty * 4];
            *(float4*)xv = *(float4*)&xs[c * 64 + tx * 4];
            #pragma unroll
            for (int i = 0; i < 4; i++)
                #pragma unroll
                for (int j = 0; j < 4; j++)
                    acc[i][j] += wv[i] * xv[j];
        }

        if (which < 2) {
            #pragma unroll
            for (int j = 0; j < 4; j++) {
                int nl = tx * 4 + j;
                #pragma unroll
                for (int i = 0; i < 4; i++) {
                    int o = ty * 4 + i;
                    float v = acc[i][j] + bs[o];
                    __nv_bfloat16 h = __float2bfloat16(v);
                    tsh[nl * PIT + o] = h;
                    tsl[nl * PIT + o] = __float2bfloat16(v - __bfloat162float(h));
                }
            }
            __syncthreads();
            for (int idx = t; idx < 64 * 8; idx += 256) {
                int row = idx >> 3, c8 = idx & 7;
                *(uint4*)&th[n0 + nc + row][c8 * 8] = *(uint4*)&tsh[row * PIT + c8 * 8];
                *(uint4*)&tl[n0 + nc + row][c8 * 8] = *(uint4*)&tsl[row * PIT + c8 * 8];
            }
        } else {
            #pragma unroll
            for (int i = 0; i < 4; i++) {
                int o = ty * 4 + i;
                float bb = bs[o];
                float v0 = acc[i][0] + bb, v1 = acc[i][1] + bb;
                float v2 = acc[i][2] + bb, v3 = acc[i][3] + bb;
                uint2 hp, lp;
                hp.x = cvtb2(v0, v1);
                hp.y = cvtb2(v2, v3);
                float h0 = __uint_as_float(hp.x << 16);
                float h1 = __uint_as_float(hp.x & 0xFFFF0000u);
                float h2 = __uint_as_float(hp.y << 16);
                float h3 = __uint_as_float(hp.y & 0xFFFF0000u);
                lp.x = cvtb2(v0 - h0, v1 - h1);
                lp.y = cvtb2(v2 - h2, v3 - h3);
                *(uint2*)&g_vh[br][b][o][n0 + nc + tx * 4] = hp;
                *(uint2*)&g_vl[br][b][o][n0 + nc + tx * 4] = lp;
            }
        }
    }
}

// ---------------------------------------------------------------------------
// Kernel 2: row stats  c_i = log2( sum_j exp(s_ij) )
// Single barrier per iteration; B operands via ldsm4 (2 n-tiles per load).
// ---------------------------------------------------------------------------
__global__ void __launch_bounds__(256, 2) stats_kernel() {
    extern __shared__ char dyn[];
    __shared__ float zbuf[128];

    int t = threadIdx.x, w = t >> 5, lane = t & 31;
    int rg = w >> 1, cg = w & 1;
    int i0 = blockIdx.x * 128, br = blockIdx.y, b = blockIdx.z;

    uint32_t base = smem_u32(dyn);
    if (t < 128) zbuf[t] = 0.f;

    for (int idx = t; idx < 128 * 8; idx += 256) {
        int row = idx >> 3, c8 = idx & 7;
        uint32_t off = row * PITB + c8 * 16;
        cp16(base + REG + off,        &g_qth[br][b][i0 + row][c8 * 8]);
        cp16(base + REG + 18432 + off,&g_qtl[br][b][i0 + row][c8 * 8]);
        cp16(base + off,              &g_kth[br][b][row][c8 * 8]);
        cp16(base + 18432 + off,      &g_ktl[br][b][row][c8 * 8]);
    }
    CP_COMMIT();
    CP_WAIT0();
    __syncthreads();

    uint32_t aQh[2][4][4], aQl[2][4][4];
    #pragma unroll
    for (int m = 0; m < 2; m++) {
        uint32_t ah = base + REG +         (32 * rg + 16 * m + (lane & 15)) * PITB + (lane >> 4) * 16;
        uint32_t al = base + REG + 18432 + (32 * rg + 16 * m + (lane & 15)) * PITB + (lane >> 4) * 16;
        #pragma unroll
        for (int k = 0; k < 4; k++) { ldsm4(aQh[m][k], ah + k * 32); ldsm4(aQl[m][k], al + k * 32); }
    }

    uint32_t boff4 = (lane & 7) * PITB + ((lane >> 3) & 1) * 16 + (lane >> 4) * (8 * PITB);
    float zr[4] = {0.f, 0.f, 0.f, 0.f};

    for (int jt = 0; jt < 32; jt++) {
        uint32_t cur = base + (jt & 1) * REG;
        uint32_t nxt = base + ((jt + 1) & 1) * REG;

        CP_WAIT0();
        __syncthreads();

        if (jt + 1 < 32) {
            for (int idx = t; idx < 128 * 8; idx += 256) {
                int row = idx >> 3, c8 = idx & 7;
                uint32_t off = row * PITB + c8 * 16;
                cp16(nxt + off,         &g_kth[br][b][(jt + 1) * 128 + row][c8 * 8]);
                cp16(nxt + 18432 + off, &g_ktl[br][b][(jt + 1) * 128 + row][c8 * 8]);
            }
            CP_COMMIT();
        }

        uint32_t kh0 = cur, kl0 = cur + 18432;

        #pragma unroll
        for (int np = 0; np < 4; np++) {
            float s4[2][2][4] = {};
            #pragma unroll
            for (int k = 0; k < 4; k++) {
                uint32_t bh[4], bl[4];
                uint32_t cb = (64 * cg + 16 * np) * PITB + boff4 + k * 32;
                ldsm4(bh, kh0 + cb);
                ldsm4(bl, kl0 + cb);
                #pragma unroll
                for (int p = 0; p < 2; p++)
                    #pragma unroll
                    for (int m = 0; m < 2; m++) mma_bf16(s4[p][m], aQh[m][k], &bh[2 * p]);
                #pragma unroll
                for (int p = 0; p < 2; p++)
                    #pragma unroll
                    for (int m = 0; m < 2; m++) mma_bf16(s4[p][m], aQh[m][k], &bl[2 * p]);
                #pragma unroll
                for (int p = 0; p < 2; p++)
                    #pragma unroll
                    for (int m = 0; m < 2; m++) mma_bf16(s4[p][m], aQl[m][k], &bh[2 * p]);
            }
            #pragma unroll
            for (int p = 0; p < 2; p++)
                #pragma unroll
                for (int m = 0; m < 2; m++) {
                    zr[m * 2 + 0] += ex2f(s4[p][m][0] * L2E) + ex2f(s4[p][m][1] * L2E);
                    zr[m * 2 + 1] += ex2f(s4[p][m][2] * L2E) + ex2f(s4[p][m][3] * L2E);
                }
        }
    }

    #pragma unroll
    for (int q = 0; q < 4; q++) {
        zr[q] += __shfl_xor_sync(0xffffffffu, zr[q], 1);
        zr[q] += __shfl_xor_sync(0xffffffffu, zr[q], 2);
    }
    if ((lane & 3) == 0) {
        int rbase = 32 * rg + (lane >> 2);
        atomicAdd(&zbuf[rbase],      zr[0]);
        atomicAdd(&zbuf[rbase + 8],  zr[1]);
        atomicAdd(&zbuf[rbase + 16], zr[2]);
        atomicAdd(&zbuf[rbase + 24], zr[3]);
    }
    __syncthreads();
    if (t < 128) g_c[br][b][i0 + t] = __log2f(zbuf[t]);
}

// ---------------------------------------------------------------------------
// Kernel 3: O[j][c] = sum_i 2^(s[j][i]*L2E - c_i) * v[c][i]
// P in registers; B operands via ldsm4. One barrier per iteration.
// ---------------------------------------------------------------------------
__global__ void __launch_bounds__(256, 2) pv_kernel() {
    extern __shared__ char dyn[];
    __shared__ float cs[2][64];

    int t = threadIdx.x, w = t >> 5, lane = t & 31;
    int j0 = blockIdx.x * 128, br = blockIdx.y, b = blockIdx.z;

    uint32_t base = smem_u32(dyn);

    for (int idx = t; idx < 128 * 8; idx += 256) {
        int row = idx >> 3, c8 = idx & 7;
        uint32_t off = row * PITB + c8 * 16;
        cp16(base + off,         &g_kth[br][b][j0 + row][c8 * 8]);
        cp16(base + 18432 + off, &g_ktl[br][b][j0 + row][c8 * 8]);
    }
    for (int idx = t; idx < 64 * 8; idx += 256) {
        int row = idx >> 3, c8 = idx & 7;
        uint32_t off = row * PITB + c8 * 16;
        cp16(base + REG + off,         &g_qth[br][b][row][c8 * 8]);
        cp16(base + REG + 9216 + off,  &g_qtl[br][b][row][c8 * 8]);
        cp16(base + REG + 18432 + off, &g_vh[br][b][row][c8 * 8]);
        cp16(base + REG + 27648 + off, &g_vl[br][b][row][c8 * 8]);
    }
    CP_COMMIT();
    if (t < 64) cs[0][t] = g_c[br][b][t];
    CP_WAIT0();
    __syncthreads();

    uint32_t aKh[4][4], aKl[4][4];
    {
        uint32_t ah = base +         (16 * w + (lane & 15)) * PITB + (lane >> 4) * 16;
        uint32_t al = base + 18432 + (16 * w + (lane & 15)) * PITB + (lane >> 4) * 16;
        #pragma unroll
        for (int k = 0; k < 4; k++) { ldsm4(aKh[k], ah + k * 32); ldsm4(aKl[k], al + k * 32); }
    }

    uint32_t boff4 = (lane & 7) * PITB + ((lane >> 3) & 1) * 16 + (lane >> 4) * (8 * PITB);
    float oacc[8][4] = {};

    for (int it = 0; it < 64; it++) {
        uint32_t cur = base + ((it & 1) ? 0 : REG);
        uint32_t nxt = base + ((it & 1) ? REG : 0);

        CP_WAIT0();
        __syncthreads();

        if (it + 1 < 64) {
            int i1 = (it + 1) * 64;
            for (int idx = t; idx < 64 * 8; idx += 256) {
                int row = idx >> 3, c8 = idx & 7;
                uint32_t off = row * PITB + c8 * 16;
                cp16(nxt + off,         &g_qth[br][b][i1 + row][c8 * 8]);
                cp16(nxt + 9216 + off,  &g_qtl[br][b][i1 + row][c8 * 8]);
                cp16(nxt + 18432 + off, &g_vh[br][b][row][i1 + c8 * 8]);
                cp16(nxt + 27648 + off, &g_vl[br][b][row][i1 + c8 * 8]);
            }
            CP_COMMIT();
            if (t < 64) cs[(it + 1) & 1][t] = g_c[br][b][i1 + t];
        }

        uint32_t qh0 = cur, ql0 = cur + 9216;
        uint32_t vh0 = cur + 18432, vl0 = cur + 27648;
        const float* csc = cs[it & 1];

        #pragma unroll
        for (int h = 0; h < 2; h++) {
            float s4[4][4] = {};
            #pragma unroll
            for (int k = 0; k < 4; k++) {
                uint32_t bh[2][4], bl[2][4];
                #pragma unroll
                for (int qp = 0; qp < 2; qp++) {
                    uint32_t cb = (8 * (4 * h + 2 * qp)) * PITB + boff4 + k * 32;
                    ldsm4(bh[qp], qh0 + cb);
                    ldsm4(bl[qp], ql0 + cb);
                }
                #pragma unroll
                for (int q = 0; q < 4; q++) mma_bf16(s4[q], aKh[k], &bh[q >> 1][2 * (q & 1)]);
                #pragma unroll
                for (int q = 0; q < 4; q++) mma_bf16(s4[q], aKh[k], &bl[q >> 1][2 * (q & 1)]);
                #pragma unroll
                for (int q = 0; q < 4; q++) mma_bf16(s4[q], aKl[k], &bh[q >> 1][2 * (q & 1)]);
            }

            #pragma unroll
            for (int kc = 0; kc < 2; kc++) {
                uint32_t aP[4], aPl[4];
                #pragma unroll
                for (int qq = 0; qq < 2; qq++) {
                    int q = 2 * kc + qq;
                    int col = 8 * (4 * h + q) + 2 * (lane & 3);
                    float2 cc = *(float2*)&csc[col];
                    float p0 = ex2f(fmaf(s4[q][0], L2E, -cc.x));
                    float p1 = ex2f(fmaf(s4[q][1], L2E, -cc.y));
                    float p2 = ex2f(fmaf(s4[q][2], L2E, -cc.x));
                    float p3 = ex2f(fmaf(s4[q][3], L2E, -cc.y));
                    uint32_t u01 = cvtb2(p0, p1);
                    uint32_t u23 = cvtb2(p2, p3);
                    aP[qq * 2 + 0] = u01;
                    aP[qq * 2 + 1] = u23;
                    float h0 = __uint_as_float(u01 << 16);
                    float h1 = __uint_as_float(u01 & 0xFFFF0000u);
                    float h2 = __uint_as_float(u23 << 16);
                    float h3 = __uint_as_float(u23 & 0xFFFF0000u);
                    aPl[qq * 2 + 0] = cvtb2(p0 - h0, p1 - h1);
                    aPl[qq * 2 + 1] = cvtb2(p2 - h2, p3 - h3);
                }

                uint32_t kb = (uint32_t)(64 * h + 32 * kc);
                #pragma unroll
                for (int cg2 = 0; cg2 < 2; cg2++) {
                    uint32_t bVh[2][4], bVl[2][4];
                    #pragma unroll
                    for (int cp = 0; cp < 2; cp++) {
                        uint32_t cb = (8 * (4 * cg2 + 2 * cp)) * PITB + boff4 + kb;
                        ldsm4(bVh[cp], vh0 + cb);
                        ldsm4(bVl[cp], vl0 + cb);
                    }
                    #pragma unroll
                    for (int c4 = 0; c4 < 4; c4++)
                        mma_bf16(oacc[4 * cg2 + c4], aP, &bVh[c4 >> 1][2 * (c4 & 1)]);
                    #pragma unroll
                    for (int c4 = 0; c4 < 4; c4++)
                        mma_bf16(oacc[4 * cg2 + c4], aP, &bVl[c4 >> 1][2 * (c4 & 1)]);
                    #pragma unroll
                    for (int c4 = 0; c4 < 4; c4++)
                        mma_bf16(oacc[4 * cg2 + c4], aPl, &bVh[c4 >> 1][2 * (c4 & 1)]);
                }
            }
        }
    }

    int jr = j0 + 16 * w + (lane >> 2);
    #pragma unroll
    for (int ct = 0; ct < 8; ct++) {
        int c0 = 8 * ct + 2 * (lane & 3);
        *(float2*)&g_ot[br][b][jr][c0]     = make_float2(oacc[ct][0], oacc[ct][1]);
        *(float2*)&g_ot[br][b][jr + 8][c0] = make_float2(oacc[ct][2], oacc[ct][3]);
    }
}

// ---------------------------------------------------------------------------
// Kernel 4: final fuse conv, 64-token chunks -> grid (64,4) = 256 CTAs, 1 wave
// ---------------------------------------------------------------------------
__global__ void __launch_bounds__(256, 2) final_kernel(const float* __restrict__ Wf,
                             const float* __restrict__ bf,
                             const float* __restrict__ g1p,
                             const float* __restrict__ g2p,
                             float* __restrict__ y) {
    extern __shared__ float smf[];
    float (*Wt)[64] = (float(*)[64])smf;
    float (*csm)[68] = (float(*)[68])(smf + 128 * 64);
    float* bs = smf + 128 * 64 + 128 * 68;

    int t = threadIdx.x;
    int b = blockIdx.y;
    int n0 = blockIdx.x * 64;
    float gg1 = *g1p, gg2 = *g2p;

    for (int idx = t; idx < 64 * 128; idx += 256) {
        int o = idx >> 7, c = idx & 127;
        Wt[c][o] = Wf[idx];
    }
    if (t < 64) bs[t] = bf[t];

    int tx = t & 15, ty = t >> 4;
    // stage O^T -> csm[c][n] (transpose), scaled by g1/g2
    for (int idx = t; idx < 2048; idx += 256) {
        int br2 = idx >> 10, rem = idx & 1023, n = rem >> 4, c4 = rem & 15;
        float4 v4 = *(const float4*)&g_ot[br2][b][n0 + n][c4 * 4];
        float g = br2 ? gg2 : gg1;
        csm[br2 * 64 + c4 * 4 + 0][n] = v4.x * g;
        csm[br2 * 64 + c4 * 4 + 1][n] = v4.y * g;
        csm[br2 * 64 + c4 * 4 + 2][n] = v4.z * g;
        csm[br2 * 64 + c4 * 4 + 3][n] = v4.w * g;
    }
    __syncthreads();

    float acc[4][4] = {};
    #pragma unroll 8
    for (int c = 0; c < 128; c++) {
        float wv[4], xv[4];
        *(float4*)wv = *(float4*)&Wt[c][ty * 4];
        *(float4*)xv = *(float4*)&csm[c][tx * 4];
        #pragma unroll
        for (int i = 0; i < 4; i++)
            #pragma unroll
            for (int j = 0; j < 4; j++)
                acc[i][j] += wv[i] * xv[j];
    }
    #pragma unroll
    for (int i = 0; i < 4; i++) {
        int o = ty * 4 + i;
        float bb = bs[o];
        float4 r = make_float4(acc[i][0] + bb, acc[i][1] + bb,
                               acc[i][2] + bb, acc[i][3] + bb);
        *(float4*)&y[(size_t)b * 64 * NTOK + o * NTOK + n0 + tx * 4] = r;
    }
}

// ---------------------------------------------------------------------------
extern "C" void kernel_launch(void* const* d_in, const int* in_sizes, int n_in,
                              void* d_out, int out_size) {
    const float* x  = (const float*)d_in[0];
    const float* g1 = (const float*)d_in[13];
    const float* g2 = (const float*)d_in[14];
    const float* Wf = (const float*)d_in[15];
    const float* bf = (const float*)d_in[16];
    float* y = (float*)d_out;

    ProjArgs pa;
    for (int mi = 0; mi < 6; mi++) {
        pa.W[mi] = (const float*)d_in[1 + 2 * mi];
        pa.B[mi] = (const float*)d_in[2 + 2 * mi];
    }

    const int smP = (4096 + 4096 + 64) * 4 + 2 * 64 * PIT * 2;   // 51456
    const int smS = 2 * REG;                                     // 73728
    const int smV = 2 * REG;                                     // 73728
    const int smF = (128 * 64 + 128 * 68 + 64) * 4;              // 67840

    cudaFuncSetAttribute(proj_kernel,  cudaFuncAttributeMaxDynamicSharedMemorySize, smP);
    cudaFuncSetAttribute(stats_kernel, cudaFuncAttributeMaxDynamicSharedMemorySize, smS);
    cudaFuncSetAttribute(pv_kernel,    cudaFuncAttributeMaxDynamicSharedMemorySize, smV);
    cudaFuncSetAttribute(final_kernel, cudaFuncAttributeMaxDynamicSharedMemorySize, smF);

    proj_kernel<<<dim3(16, 4, 6), 256, smP>>>(x, pa);
    stats_kernel<<<dim3(32, 2, 4), 256, smS>>>();
    pv_kernel<<<dim3(32, 2, 4), 256, smV>>>();
    final_kernel<<<dim3(64, 4), 256, smF>>>(Wf, bf, g1, g2, y);
}

// round 14
// speedup vs baseline: 1.1821x; 1.0091x over previous
#include <cuda_runtime.h>
#include <cuda_bf16.h>
#include <cstdint>

#define NTOK 4096
#define L2E  1.4426950408889634f
#define PIT  72          // smem pitch in bf16 elements
#define PITB 144         // smem pitch in bytes
#define REG  36864       // region size: 128 rows * 144B * 2 (hi+lo)

// ---------------- scratch ----------------
__device__ __nv_bfloat16 g_qth[2][4][NTOK][64];
__device__ __nv_bfloat16 g_qtl[2][4][NTOK][64];
__device__ __nv_bfloat16 g_kth[2][4][NTOK][64];
__device__ __nv_bfloat16 g_ktl[2][4][NTOK][64];
__device__ __nv_bfloat16 g_vh [2][4][64][NTOK];
__device__ __nv_bfloat16 g_vl [2][4][64][NTOK];
__device__ float g_c[2][4][NTOK];
__device__ float g_ot[2][4][NTOK][64];   // O transposed: [token j][chan c]

// ---------------- helpers ----------------
__device__ __forceinline__ uint32_t smem_u32(const void* p) {
    uint32_t a;
    asm("{ .reg .u64 t; cvta.to.shared.u64 t, %1; cvt.u32.u64 %0, t; }" : "=r"(a) : "l"(p));
    return a;
}
__device__ __forceinline__ float ex2f(float x) {
    float r; asm("ex2.approx.ftz.f32 %0, %1;" : "=f"(r) : "f"(x)); return r;
}
__device__ __forceinline__ void ldsm4(uint32_t* r, uint32_t a) {
    asm volatile("ldmatrix.sync.aligned.m8n8.x4.shared.b16 {%0,%1,%2,%3}, [%4];"
                 : "=r"(r[0]), "=r"(r[1]), "=r"(r[2]), "=r"(r[3]) : "r"(a));
}
__device__ __forceinline__ void mma_bf16(float* c, const uint32_t* a, const uint32_t* b) {
    asm volatile("mma.sync.aligned.m16n8k16.row.col.f32.bf16.bf16.f32 "
                 "{%0,%1,%2,%3}, {%4,%5,%6,%7}, {%8,%9}, {%0,%1,%2,%3};"
                 : "+f"(c[0]), "+f"(c[1]), "+f"(c[2]), "+f"(c[3])
                 : "r"(a[0]), "r"(a[1]), "r"(a[2]), "r"(a[3]), "r"(b[0]), "r"(b[1]));
}
// packed bf16x2 convert: lo = a, hi = b (rn rounding)
__device__ __forceinline__ uint32_t cvtb2(float a, float b) {
    uint32_t r;
    asm("cvt.rn.bf16x2.f32 %0, %1, %2;" : "=r"(r) : "f"(b), "f"(a));
    return r;
}
__device__ __forceinline__ void cp16(uint32_t d, const void* s) {
    asm volatile("cp.async.cg.shared.global [%0], [%1], 16;" :: "r"(d), "l"(s));
}
#define CP_COMMIT() asm volatile("cp.async.commit_group;" ::: "memory")
#define CP_WAIT0()  asm volatile("cp.async.wait_group 0;" ::: "memory")

// ---------------------------------------------------------------------------
// Kernel 1: fused projections -> bf16 hi/lo in MMA-ready (k-contiguous) layouts
// cp.async double-buffered x tiles; 3 CTAs/SM; grid 384 = single wave.
// smem: Wt 16K | bs 256 | xs0 16K | xs1 16K | tsh 9216 | tsl 9216 = 67840 B
// ---------------------------------------------------------------------------
struct ProjArgs { const float* W[6]; const float* B[6]; };

__global__ void __launch_bounds__(256, 3) proj_kernel(const float* __restrict__ x, ProjArgs pa) {
    extern __shared__ char dsm[];
    float* Wt  = (float*)dsm;               // [64][64] Wt[c][o]
    float* bs  = Wt + 4096;                 // [64]
    float* xs0 = bs + 64;                   // [64][64]
    float* xs1 = xs0 + 4096;                // [64][64]
    __nv_bfloat16* tsh = (__nv_bfloat16*)(xs1 + 4096);
    __nv_bfloat16* tsl = tsh + 64 * PIT;

    int t = threadIdx.x;
    int b = blockIdx.y;
    int n0 = blockIdx.x * 256;
    int z = blockIdx.z, br = z / 3, which = z % 3;
    const float* W = pa.W[z];
    const float* bias = pa.B[z];

    const float* xb = x + (size_t)b * 64 * NTOK;
    uint32_t xs0a = smem_u32(xs0), xs1a = smem_u32(xs1);

    // prologue: xs0 <- chunk 0 via cp.async (overlaps with Wt load below)
    for (int idx = t; idx < 1024; idx += 256) {
        int c = idx >> 4, n4 = idx & 15;
        cp16(xs0a + (uint32_t)(c * 256 + n4 * 16), &xb[c * NTOK + n0 + n4 * 4]);
    }
    CP_COMMIT();

    for (int idx = t; idx < 64 * 64; idx += 256) {
        int o = idx >> 6, c = idx & 63;
        Wt[c * 64 + o] = W[idx];
    }
    if (t < 64) bs[t] = bias[t];

    int tx = t & 15, ty = t >> 4;

    __nv_bfloat16 (*th)[64] = (which == 0) ? g_qth[br][b] : g_kth[br][b];
    __nv_bfloat16 (*tl)[64] = (which == 0) ? g_qtl[br][b] : g_ktl[br][b];

    for (int ncb = 0; ncb < 4; ncb++) {
        int nc = ncb * 64;
        float* xs = (ncb & 1) ? xs1 : xs0;
        uint32_t nxta = (ncb & 1) ? xs0a : xs1a;

        CP_WAIT0();
        __syncthreads();   // xs(cur) ready; also guards tsh/tsl + Wt reuse

        if (ncb + 1 < 4) {
            int nn = n0 + (ncb + 1) * 64;
            for (int idx = t; idx < 1024; idx += 256) {
                int c = idx >> 4, n4 = idx & 15;
                cp16(nxta + (uint32_t)(c * 256 + n4 * 16), &xb[c * NTOK + nn + n4 * 4]);
            }
            CP_COMMIT();
        }

        float acc[4][4] = {};
        #pragma unroll 8
        for (int c = 0; c < 64; c++) {
            float wv[4], xv[4];
            *(float4*)wv = *(float4*)&Wt[c * 64 + ty * 4];
            *(float4*)xv = *(float4*)&xs[c * 64 + tx * 4];
            #pragma unroll
            for (int i = 0; i < 4; i++)
                #pragma unroll
                for (int j = 0; j < 4; j++)
                    acc[i][j] += wv[i] * xv[j];
        }

        if (which < 2) {
            #pragma unroll
            for (int j = 0; j < 4; j++) {
                int nl = tx * 4 + j;
                #pragma unroll
                for (int i = 0; i < 4; i++) {
                    int o = ty * 4 + i;
                    float v = acc[i][j] + bs[o];
                    __nv_bfloat16 h = __float2bfloat16(v);
                    tsh[nl * PIT + o] = h;
                    tsl[nl * PIT + o] = __float2bfloat16(v - __bfloat162float(h));
                }
            }
            __syncthreads();
            for (int idx = t; idx < 64 * 8; idx += 256) {
                int row = idx >> 3, c8 = idx & 7;
                *(uint4*)&th[n0 + nc + row][c8 * 8] = *(uint4*)&tsh[row * PIT + c8 * 8];
                *(uint4*)&tl[n0 + nc + row][c8 * 8] = *(uint4*)&tsl[row * PIT + c8 * 8];
            }
        } else {
            #pragma unroll
            for (int i = 0; i < 4; i++) {
                int o = ty * 4 + i;
                float bb = bs[o];
                float v0 = acc[i][0] + bb, v1 = acc[i][1] + bb;
                float v2 = acc[i][2] + bb, v3 = acc[i][3] + bb;
                uint2 hp, lp;
                hp.x = cvtb2(v0, v1);
                hp.y = cvtb2(v2, v3);
                float h0 = __uint_as_float(hp.x << 16);
                float h1 = __uint_as_float(hp.x & 0xFFFF0000u);
                float h2 = __uint_as_float(hp.y << 16);
                float h3 = __uint_as_float(hp.y & 0xFFFF0000u);
                lp.x = cvtb2(v0 - h0, v1 - h1);
                lp.y = cvtb2(v2 - h2, v3 - h3);
                *(uint2*)&g_vh[br][b][o][n0 + nc + tx * 4] = hp;
                *(uint2*)&g_vl[br][b][o][n0 + nc + tx * 4] = lp;
            }
        }
    }
}

// ---------------------------------------------------------------------------
// Kernel 2: row stats  c_i = log2( sum_j exp(s_ij) )
// Single barrier per iteration; B operands via ldsm4 (2 n-tiles per load).
// ---------------------------------------------------------------------------
__global__ void __launch_bounds__(256, 2) stats_kernel() {
    extern __shared__ char dyn[];
    __shared__ float zbuf[128];

    int t = threadIdx.x, w = t >> 5, lane = t & 31;
    int rg = w >> 1, cg = w & 1;
    int i0 = blockIdx.x * 128, br = blockIdx.y, b = blockIdx.z;

    uint32_t base = smem_u32(dyn);
    if (t < 128) zbuf[t] = 0.f;

    for (int idx = t; idx < 128 * 8; idx += 256) {
        int row = idx >> 3, c8 = idx & 7;
        uint32_t off = row * PITB + c8 * 16;
        cp16(base + REG + off,        &g_qth[br][b][i0 + row][c8 * 8]);
        cp16(base + REG + 18432 + off,&g_qtl[br][b][i0 + row][c8 * 8]);
        cp16(base + off,              &g_kth[br][b][row][c8 * 8]);
        cp16(base + 18432 + off,      &g_ktl[br][b][row][c8 * 8]);
    }
    CP_COMMIT();
    CP_WAIT0();
    __syncthreads();

    uint32_t aQh[2][4][4], aQl[2][4][4];
    #pragma unroll
    for (int m = 0; m < 2; m++) {
        uint32_t ah = base + REG +         (32 * rg + 16 * m + (lane & 15)) * PITB + (lane >> 4) * 16;
        uint32_t al = base + REG + 18432 + (32 * rg + 16 * m + (lane & 15)) * PITB + (lane >> 4) * 16;
        #pragma unroll
        for (int k = 0; k < 4; k++) { ldsm4(aQh[m][k], ah + k * 32); ldsm4(aQl[m][k], al + k * 32); }
    }

    uint32_t boff4 = (lane & 7) * PITB + ((lane >> 3) & 1) * 16 + (lane >> 4) * (8 * PITB);
    float zr[4] = {0.f, 0.f, 0.f, 0.f};

    for (int jt = 0; jt < 32; jt++) {
        uint32_t cur = base + (jt & 1) * REG;
        uint32_t nxt = base + ((jt + 1) & 1) * REG;

        CP_WAIT0();
        __syncthreads();

        if (jt + 1 < 32) {
            for (int idx = t; idx < 128 * 8; idx += 256) {
                int row = idx >> 3, c8 = idx & 7;
                uint32_t off = row * PITB + c8 * 16;
                cp16(nxt + off,         &g_kth[br][b][(jt + 1) * 128 + row][c8 * 8]);
                cp16(nxt + 18432 + off, &g_ktl[br][b][(jt + 1) * 128 + row][c8 * 8]);
            }
            CP_COMMIT();
        }

        uint32_t kh0 = cur, kl0 = cur + 18432;

        #pragma unroll
        for (int np = 0; np < 4; np++) {
            float s4[2][2][4] = {};
            #pragma unroll
            for (int k = 0; k < 4; k++) {
                uint32_t bh[4], bl[4];
                uint32_t cb = (64 * cg + 16 * np) * PITB + boff4 + k * 32;
                ldsm4(bh, kh0 + cb);
                ldsm4(bl, kl0 + cb);
                #pragma unroll
                for (int p = 0; p < 2; p++)
                    #pragma unroll
                    for (int m = 0; m < 2; m++) mma_bf16(s4[p][m], aQh[m][k], &bh[2 * p]);
                #pragma unroll
                for (int p = 0; p < 2; p++)
                    #pragma unroll
                    for (int m = 0; m < 2; m++) mma_bf16(s4[p][m], aQh[m][k], &bl[2 * p]);
                #pragma unroll
                for (int p = 0; p < 2; p++)
                    #pragma unroll
                    for (int m = 0; m < 2; m++) mma_bf16(s4[p][m], aQl[m][k], &bh[2 * p]);
            }
            #pragma unroll
            for (int p = 0; p < 2; p++)
                #pragma unroll
                for (int m = 0; m < 2; m++) {
                    zr[m * 2 + 0] += ex2f(s4[p][m][0] * L2E) + ex2f(s4[p][m][1] * L2E);
                    zr[m * 2 + 1] += ex2f(s4[p][m][2] * L2E) + ex2f(s4[p][m][3] * L2E);
                }
        }
    }

    #pragma unroll
    for (int q = 0; q < 4; q++) {
        zr[q] += __shfl_xor_sync(0xffffffffu, zr[q], 1);
        zr[q] += __shfl_xor_sync(0xffffffffu, zr[q], 2);
    }
    if ((lane & 3) == 0) {
        int rbase = 32 * rg + (lane >> 2);
        atomicAdd(&zbuf[rbase],      zr[0]);
        atomicAdd(&zbuf[rbase + 8],  zr[1]);
        atomicAdd(&zbuf[rbase + 16], zr[2]);
        atomicAdd(&zbuf[rbase + 24], zr[3]);
    }
    __syncthreads();
    if (t < 128) g_c[br][b][i0 + t] = __log2f(zbuf[t]);
}

// ---------------------------------------------------------------------------
// Kernel 3: O[j][c] = sum_i 2^(s[j][i]*L2E - c_i) * v[c][i]
// P in registers; B operands via ldsm4. One barrier per iteration.
// ---------------------------------------------------------------------------
__global__ void __launch_bounds__(256, 2) pv_kernel() {
    extern __shared__ char dyn[];
    __shared__ float cs[2][64];

    int t = threadIdx.x, w = t >> 5, lane = t & 31;
    int j0 = blockIdx.x * 128, br = blockIdx.y, b = blockIdx.z;

    uint32_t base = smem_u32(dyn);

    for (int idx = t; idx < 128 * 8; idx += 256) {
        int row = idx >> 3, c8 = idx & 7;
        uint32_t off = row * PITB + c8 * 16;
        cp16(base + off,         &g_kth[br][b][j0 + row][c8 * 8]);
        cp16(base + 18432 + off, &g_ktl[br][b][j0 + row][c8 * 8]);
    }
    for (int idx = t; idx < 64 * 8; idx += 256) {
        int row = idx >> 3, c8 = idx & 7;
        uint32_t off = row * PITB + c8 * 16;
        cp16(base + REG + off,         &g_qth[br][b][row][c8 * 8]);
        cp16(base + REG + 9216 + off,  &g_qtl[br][b][row][c8 * 8]);
        cp16(base + REG + 18432 + off, &g_vh[br][b][row][c8 * 8]);
        cp16(base + REG + 27648 + off, &g_vl[br][b][row][c8 * 8]);
    }
    CP_COMMIT();
    if (t < 64) cs[0][t] = g_c[br][b][t];
    CP_WAIT0();
    __syncthreads();

    uint32_t aKh[4][4], aKl[4][4];
    {
        uint32_t ah = base +         (16 * w + (lane & 15)) * PITB + (lane >> 4) * 16;
        uint32_t al = base + 18432 + (16 * w + (lane & 15)) * PITB + (lane >> 4) * 16;
        #pragma unroll
        for (int k = 0; k < 4; k++) { ldsm4(aKh[k], ah + k * 32); ldsm4(aKl[k], al + k * 32); }
    }

    uint32_t boff4 = (lane & 7) * PITB + ((lane >> 3) & 1) * 16 + (lane >> 4) * (8 * PITB);
    float oacc[8][4] = {};

    for (int it = 0; it < 64; it++) {
        uint32_t cur = base + ((it & 1) ? 0 : REG);
        uint32_t nxt = base + ((it & 1) ? REG : 0);

        CP_WAIT0();
        __syncthreads();

        if (it + 1 < 64) {
            int i1 = (it + 1) * 64;
            for (int idx = t; idx < 64 * 8; idx += 256) {
                int row = idx >> 3, c8 = idx & 7;
                uint32_t off = row * PITB + c8 * 16;
                cp16(nxt + off,         &g_qth[br][b][i1 + row][c8 * 8]);
                cp16(nxt + 9216 + off,  &g_qtl[br][b][i1 + row][c8 * 8]);
                cp16(nxt + 18432 + off, &g_vh[br][b][row][i1 + c8 * 8]);
                cp16(nxt + 27648 + off, &g_vl[br][b][row][i1 + c8 * 8]);
            }
            CP_COMMIT();
            if (t < 64) cs[(it + 1) & 1][t] = g_c[br][b][i1 + t];
        }

        uint32_t qh0 = cur, ql0 = cur + 9216;
        uint32_t vh0 = cur + 18432, vl0 = cur + 27648;
        const float* csc = cs[it & 1];

        #pragma unroll
        for (int h = 0; h < 2; h++) {
            float s4[4][4] = {};
            #pragma unroll
            for (int k = 0; k < 4; k++) {
                uint32_t bh[2][4], bl[2][4];
                #pragma unroll
                for (int qp = 0; qp < 2; qp++) {
                    uint32_t cb = (8 * (4 * h + 2 * qp)) * PITB + boff4 + k * 32;
                    ldsm4(bh[qp], qh0 + cb);
                    ldsm4(bl[qp], ql0 + cb);
                }
                #pragma unroll
                for (int q = 0; q < 4; q++) mma_bf16(s4[q], aKh[k], &bh[q >> 1][2 * (q & 1)]);
                #pragma unroll
                for (int q = 0; q < 4; q++) mma_bf16(s4[q], aKh[k], &bl[q >> 1][2 * (q & 1)]);
                #pragma unroll
                for (int q = 0; q < 4; q++) mma_bf16(s4[q], aKl[k], &bh[q >> 1][2 * (q & 1)]);
            }

            #pragma unroll
            for (int kc = 0; kc < 2; kc++) {
                uint32_t aP[4], aPl[4];
                #pragma unroll
                for (int qq = 0; qq < 2; qq++) {
                    int q = 2 * kc + qq;
                    int col = 8 * (4 * h + q) + 2 * (lane & 3);
                    float2 cc = *(float2*)&csc[col];
                    float p0 = ex2f(fmaf(s4[q][0], L2E, -cc.x));
                    float p1 = ex2f(fmaf(s4[q][1], L2E, -cc.y));
                    float p2 = ex2f(fmaf(s4[q][2], L2E, -cc.x));
                    float p3 = ex2f(fmaf(s4[q][3], L2E, -cc.y));
                    uint32_t u01 = cvtb2(p0, p1);
                    uint32_t u23 = cvtb2(p2, p3);
                    aP[qq * 2 + 0] = u01;
                    aP[qq * 2 + 1] = u23;
                    float h0 = __uint_as_float(u01 << 16);
                    float h1 = __uint_as_float(u01 & 0xFFFF0000u);
                    float h2 = __uint_as_float(u23 << 16);
                    float h3 = __uint_as_float(u23 & 0xFFFF0000u);
                    aPl[qq * 2 + 0] = cvtb2(p0 - h0, p1 - h1);
                    aPl[qq * 2 + 1] = cvtb2(p2 - h2, p3 - h3);
                }

                uint32_t kb = (uint32_t)(64 * h + 32 * kc);
                #pragma unroll
                for (int cg2 = 0; cg2 < 2; cg2++) {
                    uint32_t bVh[2][4], bVl[2][4];
                    #pragma unroll
                    for (int cp = 0; cp < 2; cp++) {
                        uint32_t cb = (8 * (4 * cg2 + 2 * cp)) * PITB + boff4 + kb;
                        ldsm4(bVh[cp], vh0 + cb);
                        ldsm4(bVl[cp], vl0 + cb);
                    }
                    #pragma unroll
                    for (int c4 = 0; c4 < 4; c4++)
                        mma_bf16(oacc[4 * cg2 + c4], aP, &bVh[c4 >> 1][2 * (c4 & 1)]);
                    #pragma unroll
                    for (int c4 = 0; c4 < 4; c4++)
                        mma_bf16(oacc[4 * cg2 + c4], aP, &bVl[c4 >> 1][2 * (c4 & 1)]);
                    #pragma unroll
                    for (int c4 = 0; c4 < 4; c4++)
                        mma_bf16(oacc[4 * cg2 + c4], aPl, &bVh[c4 >> 1][2 * (c4 & 1)]);
                }
            }
        }
    }

    int jr = j0 + 16 * w + (lane >> 2);
    #pragma unroll
    for (int ct = 0; ct < 8; ct++) {
        int c0 = 8 * ct + 2 * (lane & 3);
        *(float2*)&g_ot[br][b][jr][c0]     = make_float2(oacc[ct][0], oacc[ct][1]);
        *(float2*)&g_ot[br][b][jr + 8][c0] = make_float2(oacc[ct][2], oacc[ct][3]);
    }
}

// ---------------------------------------------------------------------------
// Kernel 4: final fuse conv (R11 version: grid (32,4), 128-token chunks)
// ---------------------------------------------------------------------------
__global__ void __launch_bounds__(256, 2) final_kernel(const float* __restrict__ Wf,
                             const float* __restrict__ bf,
                             const float* __restrict__ g1p,
                             const float* __restrict__ g2p,
                             float* __restrict__ y) {
    extern __shared__ float smf[];
    float (*Wt)[64] = (float(*)[64])smf;
    float (*csm)[68] = (float(*)[68])(smf + 128 * 64);
    float* bs = smf + 128 * 64 + 128 * 68;

    int t = threadIdx.x;
    int b = blockIdx.y;
    int n0 = blockIdx.x * 128;
    float gg1 = *g1p, gg2 = *g2p;

    for (int idx = t; idx < 64 * 128; idx += 256) {
        int o = idx >> 7, c = idx & 127;
        Wt[c][o] = Wf[idx];
    }
    if (t < 64) bs[t] = bf[t];
    __syncthreads();

    int tx = t & 15, ty = t >> 4;
    for (int nc = 0; nc < 128; nc += 64) {
        __syncthreads();
        for (int idx = t; idx < 2048; idx += 256) {
            int br2 = idx >> 10, rem = idx & 1023, n = rem >> 4, c4 = rem & 15;
            float4 v4 = *(const float4*)&g_ot[br2][b][n0 + nc + n][c4 * 4];
            float g = br2 ? gg2 : gg1;
            csm[br2 * 64 + c4 * 4 + 0][n] = v4.x * g;
            csm[br2 * 64 + c4 * 4 + 1][n] = v4.y * g;
            csm[br2 * 64 + c4 * 4 + 2][n] = v4.z * g;
            csm[br2 * 64 + c4 * 4 + 3][n] = v4.w * g;
        }
        __syncthreads();

        float acc[4][4] = {};
        #pragma unroll 8
        for (int c = 0; c < 128; c++) {
            float wv[4], xv[4];
            *(float4*)wv = *(float4*)&Wt[c][ty * 4];
            *(float4*)xv = *(float4*)&csm[c][tx * 4];
            #pragma unroll
            for (int i = 0; i < 4; i++)
                #pragma unroll
                for (int j = 0; j < 4; j++)
                    acc[i][j] += wv[i] * xv[j];
        }
        #pragma unroll
        for (int i = 0; i < 4; i++) {
            int o = ty * 4 + i;
            float bb = bs[o];
            float4 r = make_float4(acc[i][0] + bb, acc[i][1] + bb,
                                   acc[i][2] + bb, acc[i][3] + bb);
            *(float4*)&y[(size_t)b * 64 * NTOK + o * NTOK + n0 + nc + tx * 4] = r;
        }
    }
}

// ---------------------------------------------------------------------------
extern "C" void kernel_launch(void* const* d_in, const int* in_sizes, int n_in,
                              void* d_out, int out_size) {
    const float* x  = (const float*)d_in[0];
    const float* g1 = (const float*)d_in[13];
    const float* g2 = (const float*)d_in[14];
    const float* Wf = (const float*)d_in[15];
    const float* bf = (const float*)d_in[16];
    float* y = (float*)d_out;

    ProjArgs pa;
    for (int mi = 0; mi < 6; mi++) {
        pa.W[mi] = (const float*)d_in[1 + 2 * mi];
        pa.B[mi] = (const float*)d_in[2 + 2 * mi];
    }

    const int smP = (4096 + 64 + 2 * 4096) * 4 + 2 * 64 * PIT * 2;   // 67840
    const int smS = 2 * REG;                                          // 73728
    const int smV = 2 * REG;                                          // 73728
    const int smF = (128 * 64 + 128 * 68 + 64) * 4;                   // 67840

    cudaFuncSetAttribute(proj_kernel,  cudaFuncAttributeMaxDynamicSharedMemorySize, smP);
    cudaFuncSetAttribute(stats_kernel, cudaFuncAttributeMaxDynamicSharedMemorySize, smS);
    cudaFuncSetAttribute(pv_kernel,    cudaFuncAttributeMaxDynamicSharedMemorySize, smV);
    cudaFuncSetAttribute(final_kernel, cudaFuncAttributeMaxDynamicSharedMemorySize, smF);

    proj_kernel<<<dim3(16, 4, 6), 256, smP>>>(x, pa);
    stats_kernel<<<dim3(32, 2, 4), 256, smS>>>();
    pv_kernel<<<dim3(32, 2, 4), 256, smV>>>();
    final_kernel<<<dim3(32, 4), 256, smF>>>(Wf, bf, g1, g2, y);
}